// round 7
// baseline (speedup 1.0000x reference)
#include <cuda_runtime.h>
#include <cstdint>

#define KK    9
#define CELLS 81
#define VOL   729
#define NBRD  4
#define BVOL  (VOL * NBRD)   // 2916 floats per group, 16B-aligned
#define NV4   (BVOL / 4)     // 729 float4 per group
#define NT    256
#define NBLK  592            // 4 blocks/SM * 148 SMs

__device__ __forceinline__ void cp_async16(void* smem_ptr, const void* gptr) {
    uint32_t sa = (uint32_t)__cvta_generic_to_shared(smem_ptr);
    asm volatile("cp.async.cg.shared.global [%0], [%1], 16;" :: "r"(sa), "l"(gptr));
}

__global__ void __launch_bounds__(NT, 4) sudoku_iterate_kernel(
    const float* __restrict__ s_in,
    const float* __restrict__ rm_in,
    const float* __restrict__ ri_in,
    const float* __restrict__ w_in,
    const float* __restrict__ b_in,
    float* __restrict__ s_out,
    float* __restrict__ rm_out,
    float* __restrict__ ri_out,
    int G)                                   // number of 4-board groups
{
    __shared__ float4 sS[2][NV4];            // s, double-buffered  (23.3 KB)
    __shared__ float4 sR[2][NV4];            // rm, double-buffered (23.3 KB)
    __shared__ float4 sRI[2];                // 4 ri values per group
    __shared__ int    sh_cell0[NBRD];
    __shared__ int    sh_e0[NBRD];
    __shared__ float  sh_mval[NBRD];
    __shared__ float  sh_cmc[NBRD];

    const int blk  = blockIdx.x;
    const int t    = threadIdx.x;
    const int wid  = t >> 5, lane = t & 31;
    const bool has2 = (t < NV4 - 2 * NT);    // t < 217

    const float cb  = b_in[0];
    const float cme = fminf(fmaxf(cb, 0.0f), 1.0f);
    float w[KK];
    #pragma unroll
    for (int n = 0; n < KK; n++) w[n] = w_in[n];

    if (blk >= G) return;

    // stage loads for group gg into buffer b
    auto issue_loads = [&](int gg, int b) {
        const float4* s4p = (const float4*)(s_in + (long)gg * BVOL);
        const float4* r4p = (const float4*)(rm_in + (long)gg * BVOL);
        cp_async16(&sS[b][t],      s4p + t);
        cp_async16(&sR[b][t],      r4p + t);
        cp_async16(&sS[b][t + NT], s4p + t + NT);
        cp_async16(&sR[b][t + NT], r4p + t + NT);
        if (has2) {
            cp_async16(&sS[b][t + 2 * NT], s4p + t + 2 * NT);
            cp_async16(&sR[b][t + 2 * NT], r4p + t + 2 * NT);
        }
        if (t == 0) cp_async16(&sRI[b], ri_in + (long)gg * NBRD);
    };

    // ---- prologue: stage first group ----
    issue_loads(blk, 0);
    asm volatile("cp.async.commit_group;" ::: "memory");

    int buf = 0;
    for (int g = blk; g < G; g += NBLK, buf ^= 1) {
        asm volatile("cp.async.wait_group 0;" ::: "memory");
        __syncthreads();                     // publish buf (also: all reads of buf^1 done)

        // ---- issue NEXT group's loads: in flight through all compute below ----
        const int gn = g + NBLK;
        if (gn < G) issue_loads(gn, buf ^ 1);
        asm volatile("cp.async.commit_group;" ::: "memory");

        // ---- decision: warps 0..3, one board each, from smem ----
        if (wid < NBRD) {
            const float* sb = (const float*)&sS[buf][0] + wid * VOL;

            float bv = -3.0e38f; int bi = 0;
            #pragma unroll
            for (int j3 = 0; j3 < 3; j3++) {
                int cell = lane + 32 * j3;
                if (cell < CELLS) {
                    float c = cb;
                    #pragma unroll
                    for (int n = 0; n < KK; n++)
                        c = fmaf(sb[n * CELLS + cell], w[n], c);
                    float nic = fmaxf(c - 1.0f, 0.0f);
                    float m0  = fminf(fmaxf(1.0f - fabsf(nic), 0.0f), 1.0f) * (-(float)KK);
                    float v   = m0 - nic;
                    if (v > bv) { bv = v; bi = cell; }   // first-max (ascending cells)
                }
            }
            #pragma unroll
            for (int off = 16; off; off >>= 1) {
                float ov = __shfl_xor_sync(0xffffffffu, bv, off);
                int   oi = __shfl_xor_sync(0xffffffffu, bi, off);
                if (ov > bv || (ov == bv && oi < bi)) { bv = ov; bi = oi; }
            }

            float mv = (lane < KK) ? sb[lane * CELLS + bi] : -3.0e38f;
            int   mi = lane;
            #pragma unroll
            for (int off = 16; off; off >>= 1) {
                float ov = __shfl_xor_sync(0xffffffffu, mv, off);
                int   oi = __shfl_xor_sync(0xffffffffu, mi, off);
                if (ov > mv || (ov == mv && oi < mi)) { mv = ov; mi = oi; }
            }

            if (lane == 0) {
                sh_cell0[wid] = bi;
                sh_e0[wid]    = wid * VOL + mi * CELLS + bi;
                sh_mval[wid]  = mv;
                sh_cmc[wid]   = fminf(fmaxf(fmaf(mv, w[mi], cb), 0.0f), 1.0f);
            }
        }
        __syncthreads();                     // publish decision

        // ---- elementwise + stores (R3-proven body, sourced from smem) ----
        const long base = (long)g * BVOL;
        float4* so4 = (float4*)(s_out + base);
        float4* ro4 = (float4*)(rm_out + base);
        const float* riv = (const float*)&sRI[buf];

        #pragma unroll
        for (int it = 0; it < 3; it++) {
            if (it == 2 && !has2) break;
            const int p = t + it * NT;
            const int e = 4 * p;
            const float4 sv = sS[buf][p];
            const float4 rv = sR[buf][p];

            const int j0 = (e >= VOL) + (e >= 2 * VOL) + (e >= 3 * VOL);
            const int j3 = (e + 3 >= VOL) + (e + 3 >= 2 * VOL) + (e + 3 >= 3 * VOL);
            const int c0 = e % CELLS;        // 729 % 81 == 0 -> board-independent

            float4 so, ro;
            if (j0 == j3) {                  // whole float4 inside one board
                const int   cell0 = sh_cell0[j0];
                const int   e0    = sh_e0[j0];
                const float mval  = sh_mval[j0];
                const float cmc   = sh_cmc[j0];
                const float ri    = riv[j0];
                #pragma unroll
                for (int k = 0; k < 4; k++) {
                    int cell = c0 + k; if (cell >= CELLS) cell -= CELLS;
                    const float s   = (&sv.x)[k];
                    const float ov  = (e + k == e0)   ? mval : 0.0f;
                    const float cm  = (cell == cell0) ? cmc  : cme;
                    const float orm = s * cm * (1.0f - ov);
                    (&so.x)[k] = s * (1.0f - orm);
                    (&ro.x)[k] = fmaxf((&rv.x)[k], fmaxf(ri * orm, (ri - 1.0f) * ov));
                }
            } else {                         // straddles a board boundary (rare)
                #pragma unroll
                for (int k = 0; k < 4; k++) {
                    const int f = e + k;
                    const int j = (f >= VOL) + (f >= 2 * VOL) + (f >= 3 * VOL);
                    int cell = c0 + k; if (cell >= CELLS) cell -= CELLS;
                    const float s   = (&sv.x)[k];
                    const float ov  = (f == sh_e0[j])       ? sh_mval[j] : 0.0f;
                    const float cm  = (cell == sh_cell0[j]) ? sh_cmc[j]  : cme;
                    const float orm = s * cm * (1.0f - ov);
                    const float ri  = riv[j];
                    (&so.x)[k] = s * (1.0f - orm);
                    (&ro.x)[k] = fmaxf((&rv.x)[k], fmaxf(ri * orm, (ri - 1.0f) * ov));
                }
            }
            so4[p] = so;
            ro4[p] = ro;
        }

        if (t < NBRD) ri_out[(long)g * NBRD + t] = riv[t] + 1.0f;
    }
}

extern "C" void kernel_launch(void* const* d_in, const int* in_sizes, int n_in,
                              void* d_out, int out_size)
{
    const float* s_in  = (const float*)d_in[0];
    const float* rm_in = (const float*)d_in[1];
    const float* ri_in = (const float*)d_in[2];
    const float* w_in  = (const float*)d_in[3];
    const float* b_in  = (const float*)d_in[4];

    const int B = in_sizes[0] / VOL;
    const int G = B / NBRD;

    float* out    = (float*)d_out;
    float* s_out  = out;
    float* rm_out = out + (long)B * VOL;
    float* ri_out = out + 2L * (long)B * VOL;

    const int nblk = (G < NBLK) ? G : NBLK;
    sudoku_iterate_kernel<<<nblk, NT>>>(s_in, rm_in, ri_in, w_in, b_in,
                                        s_out, rm_out, ri_out, G);
}

// round 8
// speedup vs baseline: 1.2692x; 1.2692x over previous
#include <cuda_runtime.h>

#define KK    9
#define CELLS 81
#define VOL   729
#define NBRD  4
#define BVOL  (VOL * NBRD)   // 2916 floats per block, 16B-aligned
#define NV4   (BVOL / 4)     // 729 float4 per block
#define NT    256

__global__ void __launch_bounds__(NT) sudoku_iterate_kernel(
    const float* __restrict__ s_in,
    const float* __restrict__ rm_in,
    const float* __restrict__ ri_in,
    const float* __restrict__ w_in,
    const float* __restrict__ b_in,
    float* __restrict__ s_out,
    float* __restrict__ rm_out,
    float* __restrict__ ri_out)
{
    __shared__ int   sh_cell0[NBRD];
    __shared__ int   sh_e0[NBRD];
    __shared__ float sh_mval[NBRD];
    __shared__ float sh_cmc[NBRD];
    __shared__ float sh_ri[NBRD];

    const int blk = blockIdx.x;
    const int t   = threadIdx.x;
    const long base = (long)blk * BVOL;

    const float4* s4p = (const float4*)(s_in + base);
    const float4* r4p = (const float4*)(rm_in + base);

    // ---- front-load ALL elementwise data before the barrier, streaming policy ----
    const bool has2 = (t < NV4 - 2 * NT);     // t < 217
    float4 s0 = __ldcs(s4p + t);
    float4 s1 = __ldcs(s4p + t + NT);
    float4 r0 = __ldcs(r4p + t);
    float4 r1 = __ldcs(r4p + t + NT);
    float4 s2 = make_float4(0,0,0,0), r2 = make_float4(0,0,0,0);
    if (has2) { s2 = __ldcs(s4p + 2 * NT + t); r2 = __ldcs(r4p + 2 * NT + t); }
    const float cb = b_in[0];

    // ---- warps 0..3: decision for boards 0..3 (default policy: reuse wanted) ----
    const int wid = t >> 5, lane = t & 31;
    if (wid < NBRD) {
        const float* sb = s_in + base + wid * VOL;
        float w[KK];
        #pragma unroll
        for (int n = 0; n < KK; n++) w[n] = w_in[n];

        float bv = -3.0e38f; int bi = 0;
        #pragma unroll
        for (int j3 = 0; j3 < 3; j3++) {
            int cell = lane + 32 * j3;
            if (cell < CELLS) {
                float c = cb;
                #pragma unroll
                for (int n = 0; n < KK; n++)
                    c = fmaf(sb[n * CELLS + cell], w[n], c);
                float nic = fmaxf(c - 1.0f, 0.0f);
                float m0  = fminf(fmaxf(1.0f - fabsf(nic), 0.0f), 1.0f) * (-(float)KK);
                float v   = m0 - nic;
                if (v > bv) { bv = v; bi = cell; }     // first-max (ascending cells)
            }
        }
        #pragma unroll
        for (int off = 16; off; off >>= 1) {
            float ov = __shfl_xor_sync(0xffffffffu, bv, off);
            int   oi = __shfl_xor_sync(0xffffffffu, bi, off);
            if (ov > bv || (ov == bv && oi < bi)) { bv = ov; bi = oi; }
        }

        float mv = (lane < KK) ? sb[lane * CELLS + bi] : -3.0e38f;
        int   mi = lane;
        #pragma unroll
        for (int off = 16; off; off >>= 1) {
            float ov = __shfl_xor_sync(0xffffffffu, mv, off);
            int   oi = __shfl_xor_sync(0xffffffffu, mi, off);
            if (ov > mv || (ov == mv && oi < mi)) { mv = ov; mi = oi; }
        }

        if (lane == 0) {
            sh_cell0[wid] = bi;
            sh_e0[wid]    = wid * VOL + mi * CELLS + bi;
            sh_mval[wid]  = mv;
            sh_cmc[wid]   = fminf(fmaxf(fmaf(mv, w[mi], cb), 0.0f), 1.0f);
            sh_ri[wid]    = ri_in[blk * NBRD + wid];
        }
    }
    __syncthreads();   // the ONLY barrier

    const float cme = fminf(fmaxf(cb, 0.0f), 1.0f);
    float4* so4 = (float4*)(s_out + base);
    float4* ro4 = (float4*)(rm_out + base);

    #pragma unroll
    for (int it = 0; it < 3; it++) {
        if (it == 2 && !has2) break;
        const int p = t + it * NT;
        const int e = 4 * p;
        const float4 sv = (it == 0) ? s0 : (it == 1) ? s1 : s2;
        const float4 rv = (it == 0) ? r0 : (it == 1) ? r1 : r2;

        const int j0 = (e >= VOL) + (e >= 2 * VOL) + (e >= 3 * VOL);
        const int j3 = (e + 3 >= VOL) + (e + 3 >= 2 * VOL) + (e + 3 >= 3 * VOL);
        const int c0 = e % CELLS;             // 729 % 81 == 0 -> board-independent

        float4 so, ro;
        if (j0 == j3) {                       // whole float4 inside one board
            const int   cell0 = sh_cell0[j0];
            const int   e0    = sh_e0[j0];
            const float mval  = sh_mval[j0];
            const float cmc   = sh_cmc[j0];
            const float ri    = sh_ri[j0];
            #pragma unroll
            for (int k = 0; k < 4; k++) {
                int cell = c0 + k; if (cell >= CELLS) cell -= CELLS;
                const float s   = (&sv.x)[k];
                const float ov  = (e + k == e0)   ? mval : 0.0f;
                const float cm  = (cell == cell0) ? cmc  : cme;
                const float orm = s * cm * (1.0f - ov);
                (&so.x)[k] = s * (1.0f - orm);
                (&ro.x)[k] = fmaxf((&rv.x)[k], fmaxf(ri * orm, (ri - 1.0f) * ov));
            }
        } else {                              // straddles a board boundary (rare)
            #pragma unroll
            for (int k = 0; k < 4; k++) {
                const int f = e + k;
                const int j = (f >= VOL) + (f >= 2 * VOL) + (f >= 3 * VOL);
                int cell = c0 + k; if (cell >= CELLS) cell -= CELLS;
                const float s   = (&sv.x)[k];
                const float ov  = (f == sh_e0[j])       ? sh_mval[j] : 0.0f;
                const float cm  = (cell == sh_cell0[j]) ? sh_cmc[j]  : cme;
                const float orm = s * cm * (1.0f - ov);
                const float ri  = sh_ri[j];
                (&so.x)[k] = s * (1.0f - orm);
                (&ro.x)[k] = fmaxf((&rv.x)[k], fmaxf(ri * orm, (ri - 1.0f) * ov));
            }
        }
        __stcs(so4 + p, so);
        __stcs(ro4 + p, ro);
    }

    if (t < NBRD) ri_out[blk * NBRD + t] = sh_ri[t] + 1.0f;
}

extern "C" void kernel_launch(void* const* d_in, const int* in_sizes, int n_in,
                              void* d_out, int out_size)
{
    const float* s_in  = (const float*)d_in[0];
    const float* rm_in = (const float*)d_in[1];
    const float* ri_in = (const float*)d_in[2];
    const float* w_in  = (const float*)d_in[3];
    const float* b_in  = (const float*)d_in[4];

    const int B = in_sizes[0] / VOL;

    float* out    = (float*)d_out;
    float* s_out  = out;
    float* rm_out = out + (long)B * VOL;
    float* ri_out = out + 2L * (long)B * VOL;

    sudoku_iterate_kernel<<<B / NBRD, NT>>>(s_in, rm_in, ri_in, w_in, b_in,
                                            s_out, rm_out, ri_out);
}

// round 10
// speedup vs baseline: 1.4854x; 1.1703x over previous
#include <cuda_runtime.h>

#define KK    9
#define CELLS 81
#define VOL   729
#define NBRD  4
#define BVOL  (VOL * NBRD)   // 2916 floats per block, 16B-aligned
#define NV4   (BVOL / 4)     // 729 float4 per block
#define NT    256

__global__ void __launch_bounds__(NT) sudoku_iterate_kernel(
    const float* __restrict__ s_in,
    const float* __restrict__ rm_in,
    const float* __restrict__ ri_in,
    const float* __restrict__ w_in,
    const float* __restrict__ b_in,
    float* __restrict__ s_out,
    float* __restrict__ rm_out,
    float* __restrict__ ri_out)
{
    __shared__ int   sh_cell0[NBRD];
    __shared__ int   sh_e0[NBRD];
    __shared__ float sh_mval[NBRD];
    __shared__ float sh_cmc[NBRD];
    __shared__ float sh_ri[NBRD];

    const int blk = blockIdx.x;
    const int t   = threadIdx.x;
    const long base = (long)blk * BVOL;

    const float4* s4p = (const float4*)(s_in + base);
    const float4* r4p = (const float4*)(rm_in + base);

    // ---- front-load ALL elementwise data before the barrier (default policy:
    //      decision warps re-hit these lines in L1) ----
    const bool has2 = (t < NV4 - 2 * NT);     // t < 217
    float4 s0 = s4p[t];
    float4 s1 = s4p[t + NT];
    float4 r0 = r4p[t];
    float4 r1 = r4p[t + NT];
    float4 s2 = make_float4(0,0,0,0), r2 = make_float4(0,0,0,0);
    if (has2) { s2 = s4p[t + 2 * NT]; r2 = r4p[t + 2 * NT]; }
    const float cb = b_in[0];

    // ---- warps 0..3: decision for boards 0..3 ----
    const int wid = t >> 5, lane = t & 31;
    if (wid < NBRD) {
        const float* sb = s_in + base + wid * VOL;
        float w[KK];
        #pragma unroll
        for (int n = 0; n < KK; n++) w[n] = w_in[n];

        float bv = -3.0e38f; int bi = 0;
        #pragma unroll
        for (int j3 = 0; j3 < 3; j3++) {
            int cell = lane + 32 * j3;
            if (cell < CELLS) {
                float c = cb;
                #pragma unroll
                for (int n = 0; n < KK; n++)
                    c = fmaf(sb[n * CELLS + cell], w[n], c);
                float nic = fmaxf(c - 1.0f, 0.0f);
                float m0  = fminf(fmaxf(1.0f - fabsf(nic), 0.0f), 1.0f) * (-(float)KK);
                float v   = m0 - nic;
                if (v > bv) { bv = v; bi = cell; }     // first-max (ascending cells)
            }
        }
        #pragma unroll
        for (int off = 16; off; off >>= 1) {
            float ov = __shfl_xor_sync(0xffffffffu, bv, off);
            int   oi = __shfl_xor_sync(0xffffffffu, bi, off);
            if (ov > bv || (ov == bv && oi < bi)) { bv = ov; bi = oi; }
        }

        float mv = (lane < KK) ? sb[lane * CELLS + bi] : -3.0e38f;
        int   mi = lane;
        #pragma unroll
        for (int off = 16; off; off >>= 1) {
            float ov = __shfl_xor_sync(0xffffffffu, mv, off);
            int   oi = __shfl_xor_sync(0xffffffffu, mi, off);
            if (ov > mv || (ov == mv && oi < mi)) { mv = ov; mi = oi; }
        }

        if (lane == 0) {
            sh_cell0[wid] = bi;
            sh_e0[wid]    = wid * VOL + mi * CELLS + bi;
            sh_mval[wid]  = mv;
            sh_cmc[wid]   = fminf(fmaxf(fmaf(mv, w[mi], cb), 0.0f), 1.0f);
            sh_ri[wid]    = ri_in[blk * NBRD + wid];
        }
    }
    __syncthreads();   // the ONLY barrier

    const float cme = fminf(fmaxf(cb, 0.0f), 1.0f);
    float4* so4 = (float4*)(s_out + base);
    float4* ro4 = (float4*)(rm_out + base);

    #pragma unroll
    for (int it = 0; it < 3; it++) {
        if (it == 2 && !has2) break;
        const int p = t + it * NT;
        const int e = 4 * p;
        const float4 sv = (it == 0) ? s0 : (it == 1) ? s1 : s2;
        const float4 rv = (it == 0) ? r0 : (it == 1) ? r1 : r2;

        const int j0 = (e >= VOL) + (e >= 2 * VOL) + (e >= 3 * VOL);
        const int j3 = (e + 3 >= VOL) + (e + 3 >= 2 * VOL) + (e + 3 >= 3 * VOL);
        const int c0 = e % CELLS;             // 729 % 81 == 0 -> board-independent

        float4 so, ro;
        if (j0 == j3) {                       // whole float4 inside one board
            const int   cell0 = sh_cell0[j0];
            const int   e0    = sh_e0[j0];
            const float mval  = sh_mval[j0];
            const float cmc   = sh_cmc[j0];
            const float ri    = sh_ri[j0];
            #pragma unroll
            for (int k = 0; k < 4; k++) {
                int cell = c0 + k; if (cell >= CELLS) cell -= CELLS;
                const float s   = (&sv.x)[k];
                const float ov  = (e + k == e0)   ? mval : 0.0f;
                const float cm  = (cell == cell0) ? cmc  : cme;
                const float orm = s * cm * (1.0f - ov);
                (&so.x)[k] = s * (1.0f - orm);
                (&ro.x)[k] = fmaxf((&rv.x)[k], fmaxf(ri * orm, (ri - 1.0f) * ov));
            }
        } else {                              // straddles a board boundary (rare)
            #pragma unroll
            for (int k = 0; k < 4; k++) {
                const int f = e + k;
                const int j = (f >= VOL) + (f >= 2 * VOL) + (f >= 3 * VOL);
                int cell = c0 + k; if (cell >= CELLS) cell -= CELLS;
                const float s   = (&sv.x)[k];
                const float ov  = (f == sh_e0[j])       ? sh_mval[j] : 0.0f;
                const float cm  = (cell == sh_cell0[j]) ? sh_cmc[j]  : cme;
                const float orm = s * cm * (1.0f - ov);
                const float ri  = sh_ri[j];
                (&so.x)[k] = s * (1.0f - orm);
                (&ro.x)[k] = fmaxf((&rv.x)[k], fmaxf(ri * orm, (ri - 1.0f) * ov));
            }
        }
        __stcs(so4 + p, so);                  // streaming stores: no reuse, don't
        __stcs(ro4 + p, ro);                  // let writes churn L2 read sectors
    }

    if (t < NBRD) ri_out[blk * NBRD + t] = sh_ri[t] + 1.0f;
}

extern "C" void kernel_launch(void* const* d_in, const int* in_sizes, int n_in,
                              void* d_out, int out_size)
{
    const float* s_in  = (const float*)d_in[0];
    const float* rm_in = (const float*)d_in[1];
    const float* ri_in = (const float*)d_in[2];
    const float* w_in  = (const float*)d_in[3];
    const float* b_in  = (const float*)d_in[4];

    const int B = in_sizes[0] / VOL;

    float* out    = (float*)d_out;
    float* s_out  = out;
    float* rm_out = out + (long)B * VOL;
    float* ri_out = out + 2L * (long)B * VOL;

    sudoku_iterate_kernel<<<B / NBRD, NT>>>(s_in, rm_in, ri_in, w_in, b_in,
                                            s_out, rm_out, ri_out);
}